// round 5
// baseline (speedup 1.0000x reference)
#include <cuda_runtime.h>
#include <cuda_bf16.h>
#include <math.h>

// ---------------------------------------------------------------------------
// NonlocalBlock, single persistent kernel.
//
// out = x*shortcut_ratio + conv1x1(read, rv)*residue_ratio, read = softplus-
// normalized full spatial attention.
//
// Structure: ALL blocks first stream out = x*shortcut_ratio (common term of
// both paths). The stream pass explicitly front-batches all 7 LDG.128s per
// thread (MLP=7) before any dependent work, to cover DRAM latency from 32
// warps/SM. The rr==0 flag load is issued at thread start and consumed after
// the stream. If rr is exactly all-zero (this dataset: RESIDUE_RATIO=0.0) we
// are done. Otherwise run the full attention path with software grid
// barriers (148 blocks = 1/SM, co-resident) and finish with
// out += read_conv*rr on the same per-thread indices.
// ---------------------------------------------------------------------------

#define BB   4
#define CIN  256
#define NN   4096          // 64*64
#define VCH  128
#define KCH  64
#define BM   (BB*2)        // 8
#define NBLK 148
#define NTHR 1024
#define TOTAL4 (BB * CIN * (NN / 4))   // 1,048,576 float4
#define STRIDE (NBLK * NTHR)           // 151,552

// Scratch (static device globals — no runtime allocation)
__device__ float g_wv[BM * VCH * NN];
__device__ float g_wk[BM * KCH * NN];
__device__ float g_rk[BM * KCH * NN];
__device__ float g_read[BM * VCH * NN];
__device__ float g_rv[BB * CIN * NN];

// Grid barrier state (self-resetting: count returns to 0 every barrier)
__device__ unsigned int g_bar_count = 0;
__device__ unsigned int g_bar_gen   = 0;

__device__ __forceinline__ void grid_barrier() {
    __syncthreads();
    if (threadIdx.x == 0) {
        __threadfence();
        unsigned int gen = *((volatile unsigned int*)&g_bar_gen);
        if (atomicAdd(&g_bar_count, 1u) == NBLK - 1u) {
            g_bar_count = 0;
            __threadfence();
            atomicAdd(&g_bar_gen, 1u);
        } else {
            while (*((volatile unsigned int*)&g_bar_gen) == gen) { }
        }
        __threadfence();
    }
    __syncthreads();
}

__global__ __launch_bounds__(NTHR, 1)
void nonlocal_kernel(const float* __restrict__ x,
                     const float* __restrict__ wv_w, const float* __restrict__ wv_b,
                     const float* __restrict__ wk_w, const float* __restrict__ wk_b,
                     const float* __restrict__ rk_w, const float* __restrict__ rk_b,
                     const float* __restrict__ rv_w, const float* __restrict__ rv_b,
                     const float* __restrict__ sc,  const float* __restrict__ rr,
                     float* __restrict__ out) {
    const int t = threadIdx.x;
    const int bid = blockIdx.x;

    // Issue the flag load NOW; consume it only after the stream pass.
    int rr_nz = 0;
    if (t < CIN) rr_nz = (__ldg(rr + t) != 0.0f) ? 1 : 0;

    // ================= Pass 1: out = x * sc (always) ======================
    // 7 statically-indexed loads per thread, ALL issued before any store.
    {
        const float4* __restrict__ x4 = (const float4*)x;
        float4* __restrict__ o4 = (float4*)out;
        const int base = bid * NTHR + t;

        float4 v[7];
        float  s[7];
        const int idx6 = base + 6 * STRIDE;
        const bool tail = (idx6 < TOTAL4);

        // Batch of independent data loads (MLP_p1 = 7)
        #pragma unroll
        for (int i = 0; i < 6; i++) v[i] = x4[base + i * STRIDE];
        v[6] = tail ? x4[idx6] : make_float4(0.f, 0.f, 0.f, 0.f);

        // Independent scale lookups (L1/const path, overlap with above)
        #pragma unroll
        for (int i = 0; i < 7; i++) {
            int c = ((base + i * STRIDE) >> 10) & 255;   // NN/4 float4/channel
            s[i] = __ldg(sc + c);
        }

        #pragma unroll
        for (int i = 0; i < 6; i++) {
            float4 ov;
            ov.x = v[i].x * s[i]; ov.y = v[i].y * s[i];
            ov.z = v[i].z * s[i]; ov.w = v[i].w * s[i];
            o4[base + i * STRIDE] = ov;
        }
        if (tail) {
            float4 ov;
            ov.x = v[6].x * s[6]; ov.y = v[6].y * s[6];
            ov.z = v[6].z * s[6]; ov.w = v[6].w * s[6];
            o4[idx6] = ov;
        }
    }

    // ================= Flag reduction =====================================
    __shared__ int s_any_nz;
    if (t == 0) s_any_nz = 0;
    __syncthreads();
    if (rr_nz) atomicOr(&s_any_nz, 1);
    __syncthreads();
    if (s_any_nz == 0) return;                    // fast path: done

    // ======================================================================
    // Slow path: full attention. (Correct, rarely taken for this dataset.)
    // ======================================================================
    __shared__ float ws[CIN];
    __shared__ float rk_s[KCH][32];
    __shared__ float wk_s[KCH][32];
    __shared__ float wv_s[VCH][32];
    __shared__ float sp_s[32][33];
    __shared__ float denom_s[32];

    // ---- Phase A: projections (wv/wk/rk 1x1 convs) ----
    for (int w = bid; w < 512 * BB; w += NBLK) {
        int o = w & 511, b = w >> 9;
        const float* wrow; float bias; float* dst;
        if (o < 256) {
            wrow = wv_w + o * CIN;         bias = wv_b[o];
            dst = g_wv + (size_t)(b * 256 + o) * NN;
        } else if (o < 384) {
            int ow = o - 256;
            wrow = wk_w + ow * CIN;        bias = wk_b[ow];
            dst = g_wk + (size_t)(b * 128 + ow) * NN;
        } else {
            int ow = o - 384;
            wrow = rk_w + ow * CIN;        bias = rk_b[ow];
            dst = g_rk + (size_t)(b * 128 + ow) * NN;
        }
        __syncthreads();
        if (t < CIN) ws[t] = wrow[t];
        __syncthreads();
        const float* xb = x + (size_t)b * CIN * NN;
        for (int n = t; n < NN; n += NTHR) {
            float acc = bias;
            #pragma unroll 8
            for (int c = 0; c < CIN; c++) acc += ws[c] * xb[(size_t)c * NN + n];
            dst[n] = acc;
        }
    }
    grid_barrier();

    // ---- Phase B: fused flash-style attention ----
    for (int tile = bid; tile < 128 * BM; tile += NBLK) {
        int qt = tile & 127, bm = tile >> 7;
        int q0 = qt * 32;
        const float* rk = g_rk + (size_t)bm * KCH * NN;
        const float* wk = g_wk + (size_t)bm * KCH * NN;
        const float* wv = g_wv + (size_t)bm * VCH * NN;

        __syncthreads();
        for (int i = t; i < KCH * 32; i += NTHR) {
            int k = i >> 5, j = i & 31;
            rk_s[k][j] = rk[(size_t)k * NN + q0 + j];
        }
        if (t < 32) denom_s[t] = 0.0f;

        float acc[4];
        #pragma unroll
        for (int j = 0; j < 4; j++) acc[j] = 0.0f;
        int v  = t >> 3;            // 0..127
        int qh = (t & 7) * 4;       // 0..28
        __syncthreads();

        for (int pt = 0; pt < NN / 32; pt++) {
            int p0 = pt * 32;
            for (int i = t; i < KCH * 32; i += NTHR) {
                int k = i >> 5, j = i & 31;
                wk_s[k][j] = wk[(size_t)k * NN + p0 + j];
            }
            for (int i = t; i < VCH * 32; i += NTHR) {
                int vv = i >> 5, j = i & 31;
                wv_s[vv][j] = wv[(size_t)vv * NN + p0 + j];
            }
            __syncthreads();
            {   // 1024 logits, one per thread
                int q = t >> 5, p = t & 31;
                float s = 0.0f;
                #pragma unroll 8
                for (int k = 0; k < KCH; k++) s += rk_s[k][q] * wk_s[k][p];
                sp_s[q][p] = (s > 20.0f) ? s : log1pf(expf(s));
            }
            __syncthreads();
            if (t < 32) {
                float d = 0.0f;
                #pragma unroll
                for (int p = 0; p < 32; p++) d += sp_s[t][p];
                denom_s[t] += d;
            }
            #pragma unroll
            for (int p = 0; p < 32; p++) {
                float wvp = wv_s[v][p];
                #pragma unroll
                for (int j = 0; j < 4; j++) acc[j] += wvp * sp_s[qh + j][p];
            }
            __syncthreads();
        }
        float* rd = g_read + (size_t)bm * VCH * NN;
        #pragma unroll
        for (int j = 0; j < 4; j++) {
            int q = qh + j;
            rd[(size_t)v * NN + q0 + q] = acc[j] / (denom_s[q] + 1e-4f);
        }
    }
    grid_barrier();

    // ---- Phase C: rv 1x1 conv ----
    for (int w = bid; w < CIN * BB; w += NBLK) {
        int o = w & 255, b = w >> 8;
        __syncthreads();
        if (t < CIN) ws[t] = rv_w[o * CIN + t];
        __syncthreads();
        float bias = rv_b[o];
        const float* rd = g_read + (size_t)b * CIN * NN;
        float* dst = g_rv + (size_t)(b * CIN + o) * NN;
        for (int n = t; n < NN; n += NTHR) {
            float acc = bias;
            #pragma unroll 8
            for (int c = 0; c < CIN; c++) acc += ws[c] * rd[(size_t)c * NN + n];
            dst[n] = acc;
        }
    }
    grid_barrier();

    // ---- Phase D: out += g_rv * rr (same per-thread indices as Pass 1) ----
    {
        float4* o4 = (float4*)out;
        const float4* rv4p = (const float4*)g_rv;
        for (int idx = bid * NTHR + t; idx < TOTAL4; idx += STRIDE) {
            int c = (idx >> 10) & 255;
            float r = __ldg(rr + c);
            float4 ov = o4[idx];
            float4 rv4 = rv4p[idx];
            ov.x += rv4.x * r; ov.y += rv4.y * r;
            ov.z += rv4.z * r; ov.w += rv4.w * r;
            o4[idx] = ov;
        }
    }
}

// ---------------------------------------------------------------------------
extern "C" void kernel_launch(void* const* d_in, const int* in_sizes, int n_in,
                              void* d_out, int out_size) {
    const float* x    = (const float*)d_in[0];
    const float* wv_w = (const float*)d_in[1];
    const float* wv_b = (const float*)d_in[2];
    const float* wk_w = (const float*)d_in[3];
    const float* wk_b = (const float*)d_in[4];
    const float* rk_w = (const float*)d_in[5];
    const float* rk_b = (const float*)d_in[6];
    const float* rv_w = (const float*)d_in[7];
    const float* rv_b = (const float*)d_in[8];
    const float* sc   = (const float*)d_in[9];
    const float* rr   = (const float*)d_in[10];
    float* out = (float*)d_out;

    nonlocal_kernel<<<NBLK, NTHR>>>(x, wv_w, wv_b, wk_w, wk_b, rk_w, rk_b,
                                    rv_w, rv_b, sc, rr, out);
}

// round 7
// speedup vs baseline: 1.0295x; 1.0295x over previous
#include <cuda_runtime.h>
#include <cuda_bf16.h>
#include <math.h>

// ---------------------------------------------------------------------------
// NonlocalBlock, two-kernel graph.
//
// out = x*shortcut_ratio + conv1x1(read, rv)*residue_ratio, read = softplus-
// normalized full spatial attention.
//
// Kernel 1 (stream_kernel): out = x*sc — the term common to both paths.
//   High-occupancy pure streaming shape: 2048x256, 2 float4/thread, uniform
//   per-block scale lookup.
// Kernel 2 (attn_kernel): persistent 148x1024. Checks rr on-device; if rr is
//   exactly all-zero (this dataset: RESIDUE_RATIO=0.0) every block exits
//   immediately. Otherwise computes the full attention path with software
//   grid barriers and finishes with out += read_conv*rr (ordered after
//   kernel 1 by stream order).
// ---------------------------------------------------------------------------

#define BB   4
#define CIN  256
#define NN   4096          // 64*64
#define VCH  128
#define KCH  64
#define BM   (BB*2)        // 8
#define NBLK 148
#define NTHR 1024
#define TOTAL4 (BB * CIN * (NN / 4))   // 1,048,576 float4
#define HALF4  (TOTAL4 / 2)            // 524,288

// Scratch (static device globals — no runtime allocation)
__device__ float g_wv[BM * VCH * NN];
__device__ float g_wk[BM * KCH * NN];
__device__ float g_rk[BM * KCH * NN];
__device__ float g_read[BM * VCH * NN];
__device__ float g_rv[BB * CIN * NN];

// Grid barrier state (self-resetting)
__device__ unsigned int g_bar_count = 0;
__device__ unsigned int g_bar_gen   = 0;

__device__ __forceinline__ void grid_barrier() {
    __syncthreads();
    if (threadIdx.x == 0) {
        __threadfence();
        unsigned int gen = *((volatile unsigned int*)&g_bar_gen);
        if (atomicAdd(&g_bar_count, 1u) == NBLK - 1u) {
            g_bar_count = 0;
            __threadfence();
            atomicAdd(&g_bar_gen, 1u);
        } else {
            while (*((volatile unsigned int*)&g_bar_gen) == gen) { }
        }
        __threadfence();
    }
    __syncthreads();
}

// ---------------------------------------------------------------------------
// Kernel 1: out = x * sc. 2048 blocks x 256 threads, 2 float4/thread.
// Each block covers 256 contiguous float4 (within one 1024-float4 channel
// group), so the channel index is uniform per block.
__global__ __launch_bounds__(256)
void stream_kernel(const float4* __restrict__ x4,
                   const float*  __restrict__ sc,
                   float4* __restrict__ o4) {
    const int idx1 = blockIdx.x * 256 + threadIdx.x;   // [0, HALF4)
    const int idx2 = idx1 + HALF4;
    // Uniform per-block channel indices (256 | 1024)
    const float s1 = __ldg(sc + ((blockIdx.x >> 2) & 255));
    const float s2 = __ldg(sc + (((blockIdx.x >> 2) + (HALF4 >> 10)) & 255));
    float4 a = x4[idx1];
    float4 b = x4[idx2];
    float4 oa, ob;
    oa.x = a.x * s1; oa.y = a.y * s1; oa.z = a.z * s1; oa.w = a.w * s1;
    ob.x = b.x * s2; ob.y = b.y * s2; ob.z = b.z * s2; ob.w = b.w * s2;
    o4[idx1] = oa;
    o4[idx2] = ob;
}

// ---------------------------------------------------------------------------
// Kernel 2: conditional attention path (persistent, 148 blocks co-resident).
__global__ __launch_bounds__(NTHR, 1)
void attn_kernel(const float* __restrict__ x,
                 const float* __restrict__ wv_w, const float* __restrict__ wv_b,
                 const float* __restrict__ wk_w, const float* __restrict__ wk_b,
                 const float* __restrict__ rk_w, const float* __restrict__ rk_b,
                 const float* __restrict__ rv_w, const float* __restrict__ rv_b,
                 const float* __restrict__ rr,
                 float* __restrict__ out) {
    const int t = threadIdx.x;
    const int bid = blockIdx.x;

    // ---- flag: exit immediately if residue_ratio is exactly all-zero ----
    __shared__ int s_any_nz;
    if (t == 0) s_any_nz = 0;
    __syncthreads();
    if (t < CIN && __ldg(rr + t) != 0.0f) atomicOr(&s_any_nz, 1);
    __syncthreads();
    if (s_any_nz == 0) return;

    __shared__ float ws[CIN];
    __shared__ float rk_s[KCH][32];
    __shared__ float wk_s[KCH][32];
    __shared__ float wv_s[VCH][32];
    __shared__ float sp_s[32][33];
    __shared__ float denom_s[32];

    // ---- Phase A: projections (wv/wk/rk 1x1 convs) ----
    for (int w = bid; w < 512 * BB; w += NBLK) {
        int o = w & 511, b = w >> 9;
        const float* wrow; float bias; float* dst;
        if (o < 256) {
            wrow = wv_w + o * CIN;         bias = wv_b[o];
            dst = g_wv + (size_t)(b * 256 + o) * NN;
        } else if (o < 384) {
            int ow = o - 256;
            wrow = wk_w + ow * CIN;        bias = wk_b[ow];
            dst = g_wk + (size_t)(b * 128 + ow) * NN;
        } else {
            int ow = o - 384;
            wrow = rk_w + ow * CIN;        bias = rk_b[ow];
            dst = g_rk + (size_t)(b * 128 + ow) * NN;
        }
        __syncthreads();
        if (t < CIN) ws[t] = wrow[t];
        __syncthreads();
        const float* xb = x + (size_t)b * CIN * NN;
        for (int n = t; n < NN; n += NTHR) {
            float acc = bias;
            #pragma unroll 8
            for (int c = 0; c < CIN; c++) acc += ws[c] * xb[(size_t)c * NN + n];
            dst[n] = acc;
        }
    }
    grid_barrier();

    // ---- Phase B: fused flash-style attention ----
    for (int tile = bid; tile < 128 * BM; tile += NBLK) {
        int qt = tile & 127, bm = tile >> 7;
        int q0 = qt * 32;
        const float* rk = g_rk + (size_t)bm * KCH * NN;
        const float* wk = g_wk + (size_t)bm * KCH * NN;
        const float* wv = g_wv + (size_t)bm * VCH * NN;

        __syncthreads();
        for (int i = t; i < KCH * 32; i += NTHR) {
            int k = i >> 5, j = i & 31;
            rk_s[k][j] = rk[(size_t)k * NN + q0 + j];
        }
        if (t < 32) denom_s[t] = 0.0f;

        float acc[4];
        #pragma unroll
        for (int j = 0; j < 4; j++) acc[j] = 0.0f;
        int v  = t >> 3;            // 0..127
        int qh = (t & 7) * 4;       // 0..28
        __syncthreads();

        for (int pt = 0; pt < NN / 32; pt++) {
            int p0 = pt * 32;
            for (int i = t; i < KCH * 32; i += NTHR) {
                int k = i >> 5, j = i & 31;
                wk_s[k][j] = wk[(size_t)k * NN + p0 + j];
            }
            for (int i = t; i < VCH * 32; i += NTHR) {
                int vv = i >> 5, j = i & 31;
                wv_s[vv][j] = wv[(size_t)vv * NN + p0 + j];
            }
            __syncthreads();
            {   // 1024 logits, one per thread
                int q = t >> 5, p = t & 31;
                float s = 0.0f;
                #pragma unroll 8
                for (int k = 0; k < KCH; k++) s += rk_s[k][q] * wk_s[k][p];
                sp_s[q][p] = (s > 20.0f) ? s : log1pf(expf(s));
            }
            __syncthreads();
            if (t < 32) {
                float d = 0.0f;
                #pragma unroll
                for (int p = 0; p < 32; p++) d += sp_s[t][p];
                denom_s[t] += d;
            }
            #pragma unroll
            for (int p = 0; p < 32; p++) {
                float wvp = wv_s[v][p];
                #pragma unroll
                for (int j = 0; j < 4; j++) acc[j] += wvp * sp_s[qh + j][p];
            }
            __syncthreads();
        }
        float* rd = g_read + (size_t)bm * VCH * NN;
        #pragma unroll
        for (int j = 0; j < 4; j++) {
            int q = qh + j;
            rd[(size_t)v * NN + q0 + q] = acc[j] / (denom_s[q] + 1e-4f);
        }
    }
    grid_barrier();

    // ---- Phase C: rv 1x1 conv ----
    for (int w = bid; w < CIN * BB; w += NBLK) {
        int o = w & 255, b = w >> 8;
        __syncthreads();
        if (t < CIN) ws[t] = rv_w[o * CIN + t];
        __syncthreads();
        float bias = rv_b[o];
        const float* rd = g_read + (size_t)b * CIN * NN;
        float* dst = g_rv + (size_t)(b * CIN + o) * NN;
        for (int n = t; n < NN; n += NTHR) {
            float acc = bias;
            #pragma unroll 8
            for (int c = 0; c < CIN; c++) acc += ws[c] * rd[(size_t)c * NN + n];
            dst[n] = acc;
        }
    }
    grid_barrier();

    // ---- Phase D: out += g_rv * rr ----
    {
        float4* o4 = (float4*)out;
        const float4* rv4p = (const float4*)g_rv;
        const int stride = NBLK * NTHR;
        for (int idx = bid * NTHR + t; idx < TOTAL4; idx += stride) {
            int c = (idx >> 10) & 255;
            float r = __ldg(rr + c);
            float4 ov = o4[idx];
            float4 rv4 = rv4p[idx];
            ov.x += rv4.x * r; ov.y += rv4.y * r;
            ov.z += rv4.z * r; ov.w += rv4.w * r;
            o4[idx] = ov;
        }
    }
}

// ---------------------------------------------------------------------------
extern "C" void kernel_launch(void* const* d_in, const int* in_sizes, int n_in,
                              void* d_out, int out_size) {
    const float* x    = (const float*)d_in[0];
    const float* wv_w = (const float*)d_in[1];
    const float* wv_b = (const float*)d_in[2];
    const float* wk_w = (const float*)d_in[3];
    const float* wk_b = (const float*)d_in[4];
    const float* rk_w = (const float*)d_in[5];
    const float* rk_b = (const float*)d_in[6];
    const float* rv_w = (const float*)d_in[7];
    const float* rv_b = (const float*)d_in[8];
    const float* sc   = (const float*)d_in[9];
    const float* rr   = (const float*)d_in[10];
    float* out = (float*)d_out;

    stream_kernel<<<HALF4 / 256, 256>>>((const float4*)x, sc, (float4*)out);
    attn_kernel<<<NBLK, NTHR>>>(x, wv_w, wv_b, wk_w, wk_b, rk_w, rk_b,
                                rv_w, rv_b, rr, out);
}